// round 2
// baseline (speedup 1.0000x reference)
#include <cuda_runtime.h>
#include <cstddef>

#define C_IN  32
#define HID   64
#define NOC   256      // total gate channels
#define KTOT  96       // C_IN * 3 taps
#define WT    64       // W chunk width
#define HDIM  256
#define WDIM  256
#define PITCH 65       // gate buffer pitch (bank-conflict pad)

typedef unsigned long long ull;

__device__ __forceinline__ float sigmoid_f(float x) {
    float e = __expf(-x);
    return __fdividef(1.0f, 1.0f + e);
}
// tanh via exp, robust at +-inf: 1 - 2/(e^{2x}+1)
__device__ __forceinline__ float tanh_f(float x) {
    return 1.0f - __fdividef(2.0f, __expf(2.0f * x) + 1.0f);
}

__device__ __forceinline__ ull pack2(float lo, float hi) {
    ull r; asm("mov.b64 %0, {%1, %2};" : "=l"(r) : "f"(lo), "f"(hi)); return r;
}
__device__ __forceinline__ void unpack2(ull v, float& lo, float& hi) {
    asm("mov.b64 {%0, %1}, %2;" : "=f"(lo), "=f"(hi) : "l"(v));
}
// packed dual-fp32 FMA: d = a*b + d (2 FMAs per instruction, 2x fp32 rate)
__device__ __forceinline__ void fma2(ull& d, ull a, ull b) {
    asm("fma.rn.f32x2 %0, %1, %2, %0;" : "+l"(d) : "l"(a), "l"(b));
}

// Smem float offsets
// wgt  [96][256]          : 24576
// bias [256]              :   256
// xs   [96][64]           :  6144
// fb/ib/gb [64][PITCH]    :  4160 each
// hcol [64]
#define OFF_WGT  0
#define OFF_BIAS (OFF_WGT + KTOT * NOC)
#define OFF_XS   (OFF_BIAS + NOC)
#define OFF_FB   (OFF_XS + KTOT * WT)
#define OFF_IB   (OFF_FB + HID * PITCH)
#define OFF_GB   (OFF_IB + HID * PITCH)
#define OFF_HC   (OFF_GB + HID * PITCH)
#define SMEM_FLOATS (OFF_HC + HID)

extern __shared__ float smem[];

__global__ void __launch_bounds__(256, 1)
rowlstm_kernel(const float* __restrict__ x,
               const float* __restrict__ Wc,
               const float* __restrict__ bc,
               float* __restrict__ out)
{
    float* wgt  = smem + OFF_WGT;
    float* bias = smem + OFF_BIAS;
    float* xs   = smem + OFF_XS;
    float* fb   = smem + OFF_FB;
    float* ib   = smem + OFF_IB;
    float* gb   = smem + OFF_GB;
    float* hcol = smem + OFF_HC;

    const int tid = threadIdx.x;
    const int bid = blockIdx.x;
    const int h = bid % HDIM;
    const int b = bid / HDIM;

    // ---- Stage weights, reordered so oc' = [i(0..63), f(64..127), g(128..191), o(192..255)]
    // (reference split order is i, f, o, g -> swap o and g blocks)
    {
        const int ocp  = tid;
        const int orig = (ocp < 128) ? ocp : ((ocp < 192) ? (ocp + 64) : (ocp - 64));
        const float* wsrc = Wc + (size_t)orig * KTOT;   // [C_IN][3] contiguous
        #pragma unroll 4
        for (int ck = 0; ck < KTOT; ck++) {
            int kh = ck % 3, c = ck / 3;
            wgt[(kh * C_IN + c) * NOC + ocp] = wsrc[ck];
        }
        bias[ocp] = bc[orig];
    }

    const int wg = tid & 31;   // w-pair index within chunk (w = 2*wg, 2*wg+1)
    const int og = tid >> 5;   // warp id == oc group; oc' base = og*24 (0..191, warp-uniform)

    float creg = 0.0f;         // per-hid cell state (valid for tid < 64)

    for (int chunk = 0; chunk < WDIM / WT; chunk++) {
        const int w0 = chunk * WT;
        __syncthreads();   // gate buffers (n-1) consumed; xs free; weights visible

        // ---- Phase A: stage x slab [kh*32+c][64] ; zero-fill H halo
        #pragma unroll
        for (int it = 0; it < 6; it++) {
            int idx = tid + it * 256;          // 0..1535 float4 slots
            int r   = idx >> 4;                // 0..95
            int c4  = idx & 15;
            int kh  = r >> 5;
            int c   = r & 31;
            int hh  = h + kh - 1;
            float4 v = make_float4(0.f, 0.f, 0.f, 0.f);
            if (hh >= 0 && hh < HDIM) {
                v = *(const float4*)(x + ((((size_t)b * C_IN + c) * HDIM + hh) * WDIM + w0 + c4 * 4));
            }
            *(float4*)(xs + r * WT + c4 * 4) = v;
        }
        // Overlap: scan previous chunk's gates (disjoint smem from xs)
        if (chunk > 0 && tid < HID) {
            const int hid = tid;
            float c = creg;
            #pragma unroll 8
            for (int w = 0; w < WT; w++) {
                float fv = fb[hid * PITCH + w];
                float iv = ib[hid * PITCH + w];
                float gv = gb[hid * PITCH + w];
                c = fv * c + iv * gv;
            }
            creg = c;
        }
        __syncthreads();

        // ---- Phase B: gate micro-GEMM. Thread tile: 2 w x 24 oc (12 f32x2 pairs over oc)
        {
            ull acc[2][12];
            const ulonglong2* bb = (const ulonglong2*)(bias + og * 24);
            #pragma unroll
            for (int q = 0; q < 6; q++) {
                ulonglong2 bv = bb[q];
                acc[0][2*q]   = bv.x;  acc[0][2*q+1] = bv.y;
                acc[1][2*q]   = bv.x;  acc[1][2*q+1] = bv.y;
            }

            #pragma unroll 6
            for (int k = 0; k < KTOT; k++) {
                float2 xv = *(const float2*)(xs + k * WT + wg * 2);
                ull x0 = pack2(xv.x, xv.x);
                ull x1 = pack2(xv.y, xv.y);
                const ulonglong2* wr = (const ulonglong2*)(wgt + k * NOC + og * 24);
                #pragma unroll
                for (int q = 0; q < 6; q++) {
                    ulonglong2 wv = wr[q];   // warp-broadcast LDS.128 (og uniform per warp)
                    fma2(acc[0][2*q],     x0, wv.x);
                    fma2(acc[1][2*q],     x1, wv.x);
                    fma2(acc[0][2*q + 1], x0, wv.y);
                    fma2(acc[1][2*q + 1], x1, wv.y);
                }
            }

            // Activations + scatter into f/i/g buffers (gate id is warp-uniform)
            #pragma unroll
            for (int wi = 0; wi < 2; wi++) {
                int w = wg * 2 + wi;
                #pragma unroll
                for (int p = 0; p < 12; p++) {
                    float v0, v1;
                    unpack2(acc[wi][p], v0, v1);
                    int oc0 = og * 24 + 2 * p;
                    {
                        int gate = oc0 >> 6, hid = oc0 & 63;
                        if (gate == 0)      ib[hid * PITCH + w] = sigmoid_f(v0);
                        else if (gate == 1) fb[hid * PITCH + w] = sigmoid_f(v0);
                        else                gb[hid * PITCH + w] = tanh_f(v0);
                    }
                    {
                        int oc1 = oc0 + 1;
                        int gate = oc1 >> 6, hid = oc1 & 63;
                        if (gate == 0)      ib[hid * PITCH + w] = sigmoid_f(v1);
                        else if (gate == 1) fb[hid * PITCH + w] = sigmoid_f(v1);
                        else                gb[hid * PITCH + w] = tanh_f(v1);
                    }
                }
            }
        }
    }

    // ---- Final: scan last chunk, compute o-gate at w = WDIM-1, produce h column
    __syncthreads();
    if (tid < HID) {
        const int hid = tid;
        float c = creg;
        #pragma unroll 8
        for (int w = 0; w < WT; w++) {
            c = fb[hid * PITCH + w] * c + ib[hid * PITCH + w] * gb[hid * PITCH + w];
        }
        // o gate uses last column of last xs chunk (w_local = WT-1 == global w 255)
        float oacc = bias[192 + hid];
        #pragma unroll 4
        for (int k = 0; k < KTOT; k++) {
            oacc += xs[k * WT + (WT - 1)] * wgt[k * NOC + 192 + hid];
        }
        hcol[hid] = sigmoid_f(oacc) * tanh_f(c);
    }
    __syncthreads();

    // ---- Broadcast write: out[b][hid][h][0..255] = hcol[hid], coalesced float4
    {
        const int hq = tid >> 6;   // 0..3
        const int w4 = tid & 63;   // float4 slot within row
        #pragma unroll
        for (int r = 0; r < 16; r++) {
            int hid = hq * 16 + r;
            float v = hcol[hid];
            float4 vv = make_float4(v, v, v, v);
            *(float4*)(out + ((((size_t)b * HID + hid) * HDIM + h) * WDIM) + w4 * 4) = vv;
        }
    }
}

extern "C" void kernel_launch(void* const* d_in, const int* in_sizes, int n_in,
                              void* d_out, int out_size)
{
    const float* x  = (const float*)d_in[0];
    const float* Wc = (const float*)d_in[1];
    const float* bc = (const float*)d_in[2];
    float* out = (float*)d_out;

    const int B = in_sizes[0] / (C_IN * HDIM * WDIM);
    const size_t smem_bytes = (size_t)SMEM_FLOATS * sizeof(float);   // ~174 KB

    static bool attr_done = false;           // idempotent host-side config only
    if (!attr_done) {
        cudaFuncSetAttribute(rowlstm_kernel,
                             cudaFuncAttributeMaxDynamicSharedMemorySize,
                             (int)smem_bytes);
        attr_done = true;
    }

    rowlstm_kernel<<<B * HDIM, 256, smem_bytes>>>(x, Wc, bc, out);
}

// round 4
// speedup vs baseline: 2.5235x; 2.5235x over previous
#include <cuda_runtime.h>
#include <cuda_bf16.h>
#include <cstdint>
#include <cstddef>

#define HDIM   256
#define WDIM   256
#define C_IN   32
#define KTOT   96
#define WT     64
#define NCHUNK 4
#define SPITCH 66
#define EPITCH 66

// ---- smem byte offsets ------------------------------------------------
#define AFRAG_BYTES (16*6*2*32*16)          // 98304: [mt16][kt6][split2][lane32][16B]
#define OFF_AFRAG 0
#define OFF_BIAS  AFRAG_BYTES               // 256 f32
#define OFF_SCR   (OFF_BIAS + 1024)         // [96][SPITCH] f32
#define OFF_BFRAG (OFF_SCR + 96*SPITCH*4)   // [split2][kt6][nt8][lane32][8B]
#define OFF_IB    (OFF_BFRAG + 2*6*8*32*8)  // i gates [64][EPITCH] f32
#define OFF_FB    (OFF_IB + 64*EPITCH*4)
#define OFF_GB    (OFF_FB + 64*EPITCH*4)
#define OFF_OS    (OFF_GB + 64*EPITCH*4)    // 64 f32 sigma(o) at w=255
#define OFF_HS    (OFF_OS + 256)            // 64 f32 h column
#define SMEM_BYTES (OFF_HS + 256)           // 200448

#define AFRAG_OFF(mt,kt,s,lane) (OFF_AFRAG + ((((mt)*6+(kt))*2+(s))*32 + (lane))*16)
#define BFRAG_OFF(s,kt,nt,lane) (OFF_BFRAG + ((((s)*6+(kt))*8+(nt))*32 + (lane))*8)

typedef unsigned int  u32;
typedef unsigned long long ull;

// ---- activations (validated: rel_err 3e-7 end-to-end in R2) -----------
static __device__ __forceinline__ float sigmoid_f(float x){
    float e = __expf(-x);
    return __fdividef(1.0f, 1.0f + e);
}
static __device__ __forceinline__ float tanh_f(float x){
    return 1.0f - __fdividef(2.0f, __expf(2.0f * x) + 1.0f);
}

static __device__ __forceinline__ void split_bf16(float v, u32& hi, u32& lo){
    __nv_bfloat16 bh = __float2bfloat16(v);
    float r = v - __bfloat162float(bh);
    __nv_bfloat16 bl = __float2bfloat16(r);
    hi = (u32)__bfloat16_as_ushort(bh);
    lo = (u32)__bfloat16_as_ushort(bl);
}
static __device__ __forceinline__ u32 pack2(u32 lo16, u32 hi16){
    return lo16 | (hi16 << 16);   // low half = even-k element (A and B consistent)
}

// mma.sync m16n8k16 row.col f32.bf16.bf16.f32 (legal on plain sm_100 target)
static __device__ __forceinline__ void mma16816(float* c, u32 a0, u32 a1, u32 a2, u32 a3,
                                                u32 b0, u32 b1){
    asm volatile("mma.sync.aligned.m16n8k16.row.col.f32.bf16.bf16.f32 "
                 "{%0,%1,%2,%3}, {%4,%5,%6,%7}, {%8,%9}, {%0,%1,%2,%3};"
                 : "+f"(c[0]), "+f"(c[1]), "+f"(c[2]), "+f"(c[3])
                 : "r"(a0), "r"(a1), "r"(a2), "r"(a3), "r"(b0), "r"(b1));
}

// gate reorder: smem oc' order [i,f,g,o]; reference conv order [i,f,o,g]
static __device__ __forceinline__ int orig_oc(int ocp){
    return (ocp < 128) ? ocp : ((ocp < 192) ? (ocp + 64) : (ocp - 64));
}
// k = kh*32 + c  ->  flat W index offset c*3 + kh
static __device__ __forceinline__ int ck_of(int k){ return (k & 31) * 3 + (k >> 5); }

extern __shared__ char smem[];

__global__ void __launch_bounds__(256, 1)
rowlstm_mma(const float* __restrict__ x,
            const float* __restrict__ Wc,
            const float* __restrict__ bc,
            float* __restrict__ out,
            int nrows)
{
    const int tid  = threadIdx.x;
    const int wid  = tid >> 5;
    const int lane = tid & 31;
    const int g    = lane >> 2;   // group id (row within tile)
    const int tg   = lane & 3;    // thread-in-group (col pairs)

    float* bias_s = (float*)(smem + OFF_BIAS);
    float* scr    = (float*)(smem + OFF_SCR);
    float* ib     = (float*)(smem + OFF_IB);
    float* fb     = (float*)(smem + OFF_FB);
    float* gb2    = (float*)(smem + OFF_GB);
    float* o_s    = (float*)(smem + OFF_OS);
    float* h_s    = (float*)(smem + OFF_HS);

    // ================= Phase 0 (once): bias + A fragments (hi/lo bf16) ====
    {
        const int ocp = tid;
        bias_s[ocp] = bc[orig_oc(ocp)];
    }
    // combos (mt 0..15, kt 0..5): combo % 8 == wid
    for (int combo = wid; combo < 96; combo += 8){
        const int mt = combo / 6, kt = combo % 6;
        const int r0 = mt * 16 + g;           // oc' rows r0, r0+8
        const int k0 = kt * 16 + 2 * tg;      // k cols k0,k0+1 and +8,+9
        const int o0 = orig_oc(r0), o1 = orig_oc(r0 + 8);
        float f00 = Wc[o0 * KTOT + ck_of(k0)];
        float f01 = Wc[o0 * KTOT + ck_of(k0 + 1)];
        float f02 = Wc[o0 * KTOT + ck_of(k0 + 8)];
        float f03 = Wc[o0 * KTOT + ck_of(k0 + 9)];
        float f10 = Wc[o1 * KTOT + ck_of(k0)];
        float f11 = Wc[o1 * KTOT + ck_of(k0 + 1)];
        float f12 = Wc[o1 * KTOT + ck_of(k0 + 8)];
        float f13 = Wc[o1 * KTOT + ck_of(k0 + 9)];
        u32 h00,l00,h01,l01,h02,l02,h03,l03,h10,l10,h11,l11,h12,l12,h13,l13;
        split_bf16(f00,h00,l00); split_bf16(f01,h01,l01);
        split_bf16(f02,h02,l02); split_bf16(f03,h03,l03);
        split_bf16(f10,h10,l10); split_bf16(f11,h11,l11);
        split_bf16(f12,h12,l12); split_bf16(f13,h13,l13);
        uint4 hi4 = make_uint4(pack2(h00,h01), pack2(h10,h11), pack2(h02,h03), pack2(h12,h13));
        uint4 lo4 = make_uint4(pack2(l00,l01), pack2(l10,l11), pack2(l02,l03), pack2(l12,l13));
        *(uint4*)(smem + AFRAG_OFF(mt,kt,0,lane)) = hi4;
        *(uint4*)(smem + AFRAG_OFF(mt,kt,1,lane)) = lo4;
    }
    __syncthreads();

    // ================= row loop (persistent CTA) ==========================
    for (int row = blockIdx.x; row < nrows; row += gridDim.x){
        const int h = row & (HDIM - 1);
        const int b = row >> 8;
        float creg = 0.0f;                      // cell state (warps 0,1)

        for (int n = 0; n < NCHUNK; n++){
            const int w0g = n * WT;

            // ---- stage x chunk -> scratch [k][w] (coalesced, halo zero)
            #pragma unroll
            for (int it = 0; it < 24; it++){
                int idx = tid + it * 256;       // 0..6143
                int k = idx >> 6, w = idx & 63;
                int hh = h + (k >> 5) - 1;
                float v = 0.0f;
                if (hh >= 0 && hh < HDIM)
                    v = x[(((size_t)b * C_IN + (k & 31)) * HDIM + hh) * WDIM + w0g + w];
                scr[k * SPITCH + w] = v;
            }
            __syncthreads();   // S1

            // ---- build B fragments (hi/lo), kt = warp-it, nt = tid>>5
            {
                const int nt = tid >> 5;
                const int w  = nt * 8 + g;
                #pragma unroll
                for (int kt = 0; kt < 6; kt++){
                    const int k0 = kt * 16 + 2 * tg;
                    float v00 = scr[k0 * SPITCH + w];
                    float v01 = scr[(k0 + 1) * SPITCH + w];
                    float v10 = scr[(k0 + 8) * SPITCH + w];
                    float v11 = scr[(k0 + 9) * SPITCH + w];
                    u32 hA,lA,hB,lB,hC,lC,hD,lD;
                    split_bf16(v00,hA,lA); split_bf16(v01,hB,lB);
                    split_bf16(v10,hC,lC); split_bf16(v11,hD,lD);
                    *(uint2*)(smem + BFRAG_OFF(0,kt,nt,lane)) = make_uint2(pack2(hA,hB), pack2(hC,hD));
                    *(uint2*)(smem + BFRAG_OFF(1,kt,nt,lane)) = make_uint2(pack2(lA,lB), pack2(lC,lD));
                }
            }
            __syncthreads();   // S2: Bfrag ready

            // ---- MMA + fused epilogue: 3 units/warp (mt, n-half)
            #pragma unroll
            for (int j = 0; j < 3; j++){
                const int u  = wid * 3 + j;     // 0..23
                const int mt = u >> 1;          // 0..11 (i,f,g)
                const int nh = u & 1;
                float acc[4][4];
                #pragma unroll
                for (int q = 0; q < 4; q++){ acc[q][0]=acc[q][1]=acc[q][2]=acc[q][3]=0.f; }

                #pragma unroll
                for (int p = 0; p < 3; p++){    // passes: (Ah,Bh),(Al,Bh),(Ah,Bl)
                    const int as = (p == 1) ? 1 : 0;
                    const int bs = (p == 2) ? 1 : 0;
                    #pragma unroll
                    for (int kt = 0; kt < 6; kt++){
                        uint4 av = *(const uint4*)(smem + AFRAG_OFF(mt,kt,as,lane));
                        #pragma unroll
                        for (int q = 0; q < 4; q++){
                            const int nt = nh * 4 + q;
                            uint2 bv = *(const uint2*)(smem + BFRAG_OFF(bs,kt,nt,lane));
                            mma16816(acc[q], av.x, av.y, av.z, av.w, bv.x, bv.y);
                        }
                    }
                }
                // epilogue: bias + activation + STS.64 into gate buffer
                const int gate = mt >> 2;                // 0=i,1=f,2=g
                const int hidb = (mt & 3) * 16;
                const float bg0 = bias_s[mt * 16 + g];
                const float bg1 = bias_s[mt * 16 + g + 8];
                float* buf = (gate == 0) ? ib : ((gate == 1) ? fb : gb2);
                #pragma unroll
                for (int q = 0; q < 4; q++){
                    const int wq = nh * 32 + q * 8 + 2 * tg;
                    float a0, a1, a2, a3;
                    if (gate < 2){
                        a0 = sigmoid_f(acc[q][0] + bg0); a1 = sigmoid_f(acc[q][1] + bg0);
                        a2 = sigmoid_f(acc[q][2] + bg1); a3 = sigmoid_f(acc[q][3] + bg1);
                    } else {
                        a0 = tanh_f(acc[q][0] + bg0); a1 = tanh_f(acc[q][1] + bg0);
                        a2 = tanh_f(acc[q][2] + bg1); a3 = tanh_f(acc[q][3] + bg1);
                    }
                    *(float2*)(buf + (hidb + g    ) * EPITCH + wq) = make_float2(a0, a1);
                    *(float2*)(buf + (hidb + g + 8) * EPITCH + wq) = make_float2(a2, a3);
                }
            }

            // ---- o gate: only last chunk, only w=255 (nt=7), warps 0..3
            if (n == NCHUNK - 1 && wid < 4){
                const int mt = 12 + wid;
                float acc[4] = {0.f, 0.f, 0.f, 0.f};
                #pragma unroll
                for (int p = 0; p < 3; p++){
                    const int as = (p == 1) ? 1 : 0;
                    const int bs = (p == 2) ? 1 : 0;
                    #pragma unroll
                    for (int kt = 0; kt < 6; kt++){
                        uint4 av = *(const uint4*)(smem + AFRAG_OFF(mt,kt,as,lane));
                        uint2 bv = *(const uint2*)(smem + BFRAG_OFF(bs,kt,7,lane));
                        mma16816(acc, av.x, av.y, av.z, av.w, bv.x, bv.y);
                    }
                }
                if (tg == 3){   // cols 2tg+1 = 7 -> w = 63 local = 255 global
                    const int oc0 = mt * 16 + g;
                    o_s[oc0 - 192]     = sigmoid_f(acc[1] + bias_s[oc0]);
                    o_s[oc0 - 192 + 8] = sigmoid_f(acc[3] + bias_s[oc0 + 8]);
                }
            }
            __syncthreads();   // S3: gates stored

            // ---- scan chunk (warps 0,1: thread = hid)
            if (wid < 2){
                const int hid = wid * 32 + lane;
                float c = creg;
                #pragma unroll 8
                for (int w = 0; w < WT; w++){
                    float fv = fb [hid * EPITCH + w];
                    float iv = ib [hid * EPITCH + w];
                    float gv = gb2[hid * EPITCH + w];
                    c = fv * c + iv * gv;
                }
                creg = c;
                if (n == NCHUNK - 1)
                    h_s[hid] = o_s[hid] * tanh_f(c);
            }
        }
        __syncthreads();   // h_s ready

        // ---- broadcast write out[b][hid][h][0..255]
        {
            const int hq = tid >> 6;
            const int w4 = tid & 63;
            #pragma unroll
            for (int r = 0; r < 16; r++){
                int hid = hq * 16 + r;
                float v = h_s[hid];
                float4 vv = make_float4(v, v, v, v);
                *(float4*)(out + (((size_t)b * 64 + hid) * HDIM + h) * WDIM + w4 * 4) = vv;
            }
        }
        __syncthreads();
    }
}

extern "C" void kernel_launch(void* const* d_in, const int* in_sizes, int n_in,
                              void* d_out, int out_size)
{
    const float* x  = (const float*)d_in[0];
    const float* Wc = (const float*)d_in[1];
    const float* bc = (const float*)d_in[2];
    float* out = (float*)d_out;

    const int B = in_sizes[0] / (C_IN * HDIM * WDIM);
    const int nrows = B * HDIM;

    static bool attr_done = false;
    if (!attr_done){
        cudaFuncSetAttribute(rowlstm_mma,
                             cudaFuncAttributeMaxDynamicSharedMemorySize,
                             SMEM_BYTES);
        attr_done = true;
    }

    int grid = 148;
    if (nrows < grid) grid = nrows;
    rowlstm_mma<<<grid, 256, SMEM_BYTES>>>(x, Wc, bc, out, nrows);
}